// round 15
// baseline (speedup 1.0000x reference)
#include <cuda_runtime.h>
#include <cuda_fp16.h>
#include <cstdint>

// ---------------- problem dims ----------------
#define MDIM 8192
#define NDIM 4096
#define KDIM 4096

// ---------------- GEMM tiling ----------------
#define BM 128
#define BN 128
#define BK 64                  // 64 fp16 = 128 B per row; tile = 16 KB
#define STAGES 3
#define KT_ITERS (KDIM / BK)   // 64
#define THREADS 128            // 4 warps: 2 (m) x 2 (n), warp tile 64x64
#define TILE_BYTES 16384
#define NTILES ((MDIM / BM) * (NDIM / BN))   // 2048
#define GRID_CTAS 296                        // 2 per SM x 148 SMs (persistent)

// SMEM: [0..1024) barriers, then 3 stages x (A 16KB | B 16KB)
#define SM_FULL(s)   ((s) * 8)
#define SM_EMPTY(s)  (64 + (s) * 8)
#define SM_TILE0     1024
#define OFF_A 0
#define OFF_B 16384
#define STAGE_BYTES 32768
#define SMEM_TOTAL (SM_TILE0 + STAGES * STAGE_BYTES)   // 99328 -> 2 CTAs/SM

// prep: one 16B unit (8 fp16) per thread
#define W_UNITS (NDIM * KDIM / 8)       // 2M
#define X_UNITS (MDIM * KDIM / 8)       // 4M
#define W_BLOCKS (W_UNITS / 256)        // 8192
#define X_BLOCKS (X_UNITS / 256)        // 16384

// ---------------- scratch: pre-swizzled 16KB-tiled layouts ----------------
// g_A: [tm (64)][kt (64)] tiles; tile = 128 rows x 128B, unit u at u^(row&7)
// g_Bw: [tn (32)][kt (64)] tiles; same form
__device__ __align__(256) char g_A [(size_t)MDIM * KDIM * 2];   // 64 MB
__device__ __align__(256) char g_Bw[(size_t)NDIM * KDIM * 2];   // 32 MB

// ---------------- PTX helpers ----------------
__device__ __forceinline__ uint32_t smem_u32(const void* p) {
    return (uint32_t)__cvta_generic_to_shared(p);
}
__device__ __forceinline__ void mbar_init(uint32_t a, uint32_t cnt) {
    asm volatile("mbarrier.init.shared.b64 [%0], %1;" :: "r"(a), "r"(cnt) : "memory");
}
__device__ __forceinline__ void mbar_arrive(uint32_t a) {
    asm volatile("mbarrier.arrive.shared.b64 _, [%0];" :: "r"(a) : "memory");
}
__device__ __forceinline__ void mbar_expect_tx(uint32_t a, uint32_t bytes) {
    asm volatile("mbarrier.arrive.expect_tx.shared.b64 _, [%0], %1;"
                 :: "r"(a), "r"(bytes) : "memory");
}
__device__ __forceinline__ void bulk_g2s(uint32_t dst, const void* src,
                                         uint32_t bytes, uint32_t mbar) {
    asm volatile(
        "cp.async.bulk.shared::cluster.global.mbarrier::complete_tx::bytes "
        "[%0], [%1], %2, [%3];"
        :: "r"(dst), "l"(src), "r"(bytes), "r"(mbar) : "memory");
}
__device__ __forceinline__ void mbar_wait(uint32_t mbar, uint32_t parity) {
    asm volatile(
        "{\n\t.reg .pred P;\n\t"
        "WL%=:\n\t"
        "mbarrier.try_wait.parity.acquire.cta.shared::cta.b64 P, [%0], %1, 0x989680;\n\t"
        "@P bra.uni WD%=;\n\t"
        "bra.uni WL%=;\n\t"
        "WD%=:\n\t}"
        :: "r"(mbar), "r"(parity) : "memory");
}
__device__ __forceinline__ void ldsm_x4(uint32_t* d, uint32_t addr) {
    asm volatile("ldmatrix.sync.aligned.m8n8.x4.shared.b16 {%0,%1,%2,%3}, [%4];"
                 : "=r"(d[0]), "=r"(d[1]), "=r"(d[2]), "=r"(d[3]) : "r"(addr));
}
__device__ __forceinline__ void mma16816(float* c, const uint32_t* a,
                                         uint32_t b0, uint32_t b1) {
    asm volatile(
        "mma.sync.aligned.m16n8k16.row.col.f32.f16.f16.f32 "
        "{%0,%1,%2,%3}, {%4,%5,%6,%7}, {%8,%9}, {%0,%1,%2,%3};"
        : "+f"(c[0]), "+f"(c[1]), "+f"(c[2]), "+f"(c[3])
        : "r"(a[0]), "r"(a[1]), "r"(a[2]), "r"(a[3]), "r"(b0), "r"(b1));
}

// ---------------- prep: emit pre-swizzled 16KB tiles ----------------
__global__ __launch_bounds__(256) void prep_kernel(const int* __restrict__ wp,
                                                   const float4* __restrict__ x4) {
    int bid = blockIdx.x;
    if (bid < W_BLOCKS) {
        int wu = bid * 256 + threadIdx.x;      // 0 .. W_UNITS-1
        int n  = wu >> 9;                      // 512 units per row (K/8)
        int ku = wu & 511;
        int4 p = reinterpret_cast<const int4*>(wp)[wu];   // 4 int32, contiguous
        __half2 h[4];
        h[0] = __floats2half2_rn((float)((p.x & 0xF) - 8),
                                 (float)(((p.x >> 4) & 0xF) - 8));
        h[1] = __floats2half2_rn((float)((p.y & 0xF) - 8),
                                 (float)(((p.y >> 4) & 0xF) - 8));
        h[2] = __floats2half2_rn((float)((p.z & 0xF) - 8),
                                 (float)(((p.z >> 4) & 0xF) - 8));
        h[3] = __floats2half2_rn((float)((p.w & 0xF) - 8),
                                 (float)(((p.w >> 4) & 0xF) - 8));
        int tn = n >> 7, row = n & 127, kt = ku >> 3, u = ku & 7;
        size_t dst = ((size_t)(tn * KT_ITERS + kt) << 14)
                   + row * 128 + ((u ^ (row & 7)) << 4);
        *reinterpret_cast<uint4*>(g_Bw + dst) = *reinterpret_cast<uint4*>(h);
    } else {
        int xu = (bid - W_BLOCKS) * 256 + threadIdx.x;    // 0 .. X_UNITS-1
        int m  = xu >> 9;
        int ku = xu & 511;
        float4 v0 = x4[2 * xu], v1 = x4[2 * xu + 1];
        __half2 h[4];
        h[0] = __floats2half2_rn(v0.x, v0.y);
        h[1] = __floats2half2_rn(v0.z, v0.w);
        h[2] = __floats2half2_rn(v1.x, v1.y);
        h[3] = __floats2half2_rn(v1.z, v1.w);
        int tm = m >> 7, row = m & 127, kt = ku >> 3, u = ku & 7;
        size_t dst = ((size_t)(tm * KT_ITERS + kt) << 14)
                   + row * 128 + ((u ^ (row & 7)) << 4);
        *reinterpret_cast<uint4*>(g_A + dst) = *reinterpret_cast<uint4*>(h);
    }
}

// ---------------- kernel: persistent fp16 GEMM, TMA-bulk mbarrier ring -------
__global__ __launch_bounds__(THREADS, 2) void gemm_kernel(
    const float* __restrict__ scales, const float* __restrict__ bias,
    float* __restrict__ out)
{
    extern __shared__ char smem[];
    const uint32_t sb = smem_u32(smem);
    const int tid = threadIdx.x;
    const int wid = tid >> 5;
    const int lane = tid & 31;
    const int bid = blockIdx.x;       // 0 .. GRID_CTAS-1

    const int warp_m = wid & 1;       // 2 groups of 64 rows
    const int warp_n = wid >> 1;      // 2 groups of 64 cols

    // per-lane ldmatrix addressing (swizzled: unit16 u ^ (row & 7))
    const int a_row = warp_m * 64 + (lane & 15);
    const int a_u0  = lane >> 4;                         // + 2*ks
    const int b_row = warp_n * 64 + (lane & 7) + ((lane >> 4) << 3);
    const int b_u0  = (lane >> 3) & 1;                   // + 2*ks

    if (tid == 0) {
        #pragma unroll
        for (int s = 0; s < STAGES; s++) {
            mbar_init(sb + SM_FULL(s), 1);     // one expect_tx producer
            mbar_init(sb + SM_EMPTY(s), 4);    // 4 warps release
        }
    }
    __syncthreads();   // barriers visible before any arrive / bulk

    // producer cursor over the flattened (tile, kt) sequence of this CTA
    int ptile = bid;
    int pkt   = STAGES - 1;   // prologue below produces kt 0..STAGES-2

    // prologue: tid0 issues bulk copies for the first tile's stages 0,1
    if (tid == 0) {
        #pragma unroll
        for (int p = 0; p < STAGES - 1; p++) {
            const char* pA = g_A  + ((size_t)((ptile >> 5) * KT_ITERS + p) << 14);
            const char* pB = g_Bw + ((size_t)((ptile & 31) * KT_ITERS + p) << 14);
            uint32_t stg = sb + SM_TILE0 + p * STAGE_BYTES;
            mbar_expect_tx(sb + SM_FULL(p), STAGE_BYTES);
            bulk_g2s(stg + OFF_A, pA, TILE_BYTES, sb + SM_FULL(p));
            bulk_g2s(stg + OFF_B, pB, TILE_BYTES, sb + SM_FULL(p));
        }
    }

    // cursors: consumer (stage 0, phase 0); producer (stage 2, phase 1:
    // first lap's empty-waits pass immediately on fresh barriers)
    int cs = 0, cph = 0;
    int ps = STAGES - 1, pph = 1;

    #pragma unroll 1
    for (int t = bid; t < NTILES; t += GRID_CTAS) {
        const int m0 = (t >> 5) * BM;
        const int n0 = (t & 31) * BN;

        float c[4][8][4];
        #pragma unroll
        for (int i = 0; i < 4; i++)
            #pragma unroll
            for (int j = 0; j < 8; j++)
                #pragma unroll
                for (int r = 0; r < 4; r++) c[i][j][r] = 0.0f;

        #pragma unroll 1
        for (int kt = 0; kt < KT_ITERS; kt++) {
            mbar_wait(sb + SM_FULL(cs), (uint32_t)cph);
            const uint32_t stg = sb + SM_TILE0 + cs * STAGE_BYTES;
            const uint32_t sA  = stg + OFF_A;
            const uint32_t sBm = stg + OFF_B;

            #pragma unroll
            for (int ks = 0; ks < 4; ks++) {
                uint32_t a[4][4], b[4][4];
                #pragma unroll
                for (int i = 0; i < 4; i++) {
                    int r = a_row + i * 16;
                    ldsm_x4(a[i], sA + r * 128 +
                            (((uint32_t)((a_u0 + 2 * ks) ^ (r & 7))) << 4));
                }
                #pragma unroll
                for (int j = 0; j < 4; j++) {
                    int r = b_row + j * 16;
                    ldsm_x4(b[j], sBm + r * 128 +
                            (((uint32_t)((b_u0 + 2 * ks) ^ (r & 7))) << 4));
                }
                #pragma unroll
                for (int i = 0; i < 4; i++) {
                    #pragma unroll
                    for (int j = 0; j < 4; j++) {
                        mma16816(c[i][2 * j],     a[i], b[j][0], b[j][1]);
                        mma16816(c[i][2 * j + 1], a[i], b[j][2], b[j][3]);
                    }
                }
            }
            // this warp is done reading stage cs
            if (lane == 0) mbar_arrive(sb + SM_EMPTY(cs));

            // produce next (tile, kt) in the flattened sequence
            if (ptile < NTILES) {
                if (tid == 0) {
                    mbar_wait(sb + SM_EMPTY(ps), (uint32_t)pph);
                    const char* pA = g_A  +
                        ((size_t)((ptile >> 5) * KT_ITERS + pkt) << 14);
                    const char* pB = g_Bw +
                        ((size_t)((ptile & 31) * KT_ITERS + pkt) << 14);
                    uint32_t pstg = sb + SM_TILE0 + ps * STAGE_BYTES;
                    mbar_expect_tx(sb + SM_FULL(ps), STAGE_BYTES);
                    bulk_g2s(pstg + OFF_A, pA, TILE_BYTES, sb + SM_FULL(ps));
                    bulk_g2s(pstg + OFF_B, pB, TILE_BYTES, sb + SM_FULL(ps));
                }
                if (++ps == STAGES) { ps = 0; pph ^= 1; }
                if (++pkt == KT_ITERS) { pkt = 0; ptile += GRID_CTAS; }
            }
            if (++cs == STAGES) { cs = 0; cph ^= 1; }
        }

        // ---------------- per-tile epilogue (per-warp): scale*acc + bias ------
        const int mrow = lane >> 2;
        const int ncol = (lane & 3) * 2;
        #pragma unroll
        for (int j = 0; j < 8; j++) {
            int n = n0 + warp_n * 64 + j * 8 + ncol;
            float2 s  = *reinterpret_cast<const float2*>(scales + n);
            float2 bb = *reinterpret_cast<const float2*>(bias + n);
            #pragma unroll
            for (int i = 0; i < 4; i++) {
                int m = m0 + warp_m * 64 + i * 16 + mrow;
                float2 v0, v1;
                v0.x = c[i][j][0] * s.x + bb.x;
                v0.y = c[i][j][1] * s.y + bb.y;
                v1.x = c[i][j][2] * s.x + bb.x;
                v1.y = c[i][j][3] * s.y + bb.y;
                *reinterpret_cast<float2*>(out + (size_t)m * NDIM + n) = v0;
                *reinterpret_cast<float2*>(out + (size_t)(m + 8) * NDIM + n) = v1;
            }
        }
    }
}

// ---------------- launch ----------------
extern "C" void kernel_launch(void* const* d_in, const int* in_sizes, int n_in,
                              void* d_out, int out_size) {
    const float* x  = (const float*)d_in[0];
    const int*   wp = (const int*)d_in[1];
    const float* sc = (const float*)d_in[2];
    const float* bi = (const float*)d_in[3];
    float* out = (float*)d_out;

    static bool attr_set = false;
    if (!attr_set) {
        cudaFuncSetAttribute(gemm_kernel,
                             cudaFuncAttributeMaxDynamicSharedMemorySize, SMEM_TOTAL);
        attr_set = true;
    }

    prep_kernel<<<W_BLOCKS + X_BLOCKS, 256>>>(wp, (const float4*)x);
    gemm_kernel<<<GRID_CTAS, THREADS, SMEM_TOTAL>>>(sc, bi, out);
}